// round 7
// baseline (speedup 1.0000x reference)
#include <cuda_runtime.h>
#include <cuda_fp16.h>
#include <math.h>
#include <stdint.h>

// B=2, H=16, S=2048, DK=64
// Inputs: Q[B,H,S,DK] f32, K[B,H,S,DK] f32, V[B,H,S,DK] f32, mask[B,1,S,S] i32
// Output: concat( O[B,H,S,DK] f32, W[B,H,S,S] f32 )

#define BATCH 2
#define HEADS 16
#define SEQ   2048
#define DKDIM 64

#define HST 72   // half-element stride for all smem tiles (144B rows)

// ---------------------------------------------------------------------------
__device__ __forceinline__ uint32_t pack2(float a, float b) {
    __half2 h = __floats2half2_rn(a, b);
    return *(uint32_t*)&h;
}

__device__ __forceinline__ void ldsm4(uint32_t r[4], const __half* p) {
    uint32_t addr = (uint32_t)__cvta_generic_to_shared(p);
    asm volatile("ldmatrix.sync.aligned.m8n8.x4.shared.b16 {%0,%1,%2,%3}, [%4];"
                 : "=r"(r[0]), "=r"(r[1]), "=r"(r[2]), "=r"(r[3]) : "r"(addr));
}

__device__ __forceinline__ void ldsm4t(uint32_t r[4], const __half* p) {
    uint32_t addr = (uint32_t)__cvta_generic_to_shared(p);
    asm volatile("ldmatrix.sync.aligned.m8n8.x4.trans.shared.b16 {%0,%1,%2,%3}, [%4];"
                 : "=r"(r[0]), "=r"(r[1]), "=r"(r[2]), "=r"(r[3]) : "r"(addr));
}

__device__ __forceinline__ void mma_f16(float c[4],
                                        const uint32_t a[4],
                                        uint32_t b0, uint32_t b1) {
    asm volatile(
        "mma.sync.aligned.m16n8k16.row.col.f32.f16.f16.f32 "
        "{%0,%1,%2,%3}, {%4,%5,%6,%7}, {%8,%9}, {%0,%1,%2,%3};\n"
        : "+f"(c[0]), "+f"(c[1]), "+f"(c[2]), "+f"(c[3])
        : "r"(a[0]), "r"(a[1]), "r"(a[2]), "r"(a[3]), "r"(b0), "r"(b1));
}

// ---------------------------------------------------------------------------
// One fused kernel. Per (bh, 128-row q tile):
//  Loop1 over 32 k-tiles: S=QK^T (fp16 mma), e=mask?exp(S/8):0, rowsum.
//  inv = 1/rowsum.
//  Loop2: recompute S, w = e*inv -> STG W (normalized), STS fp16 w,
//         accO += w @ V (fp16 mma).  O stored directly.
// 8 warps: 4(q) x 2(k|n), warp tiles 32x32.
// ---------------------------------------------------------------------------
__global__ __launch_bounds__(256)
void sdpa_fused_kernel(const float* __restrict__ Q,
                       const float* __restrict__ K,
                       const float* __restrict__ V,
                       const int*   __restrict__ mask,
                       float* __restrict__ W,
                       float* __restrict__ O)
{
    extern __shared__ __align__(16) char smraw[];
    __half* Qs = (__half*)smraw;              // [128][HST]
    __half* Ks = Qs + 128 * HST;              // [64][HST]
    __half* Vs = Ks + 64 * HST;               // [64][HST]
    __half* Ss = Vs + 64 * HST;               // [128][HST]
    float*  rs   = (float*)(Ss + 128 * HST);  // [128][2]
    float*  invs = rs + 256;                  // [128]

    const int bh   = blockIdx.y;
    const int b    = bh >> 4;
    const int q0   = blockIdx.x * 128;
    const int tid  = threadIdx.x;
    const int lane = tid & 31;
    const int warp = tid >> 5;
    const int wq   = warp >> 1;   // 0..3
    const int wk   = warp & 1;    // 0..1
    const int gid  = lane >> 2;   // 0..7
    const int tig  = lane & 3;    // 0..3

    const float* Qp = Q + ((size_t)bh * SEQ + q0) * DKDIM;
    const float* Kp = K + (size_t)bh * SEQ * DKDIM;
    const float* Vp = V + (size_t)bh * SEQ * DKDIM;

    // ---- stage Q tile (persistent, fp16) ----
    #pragma unroll
    for (int it = 0; it < 4; it++) {
        const int id  = tid + it * 256;
        const int row = id >> 3;
        const int grp = id & 7;
        const float* src = Qp + row * DKDIM + grp * 8;
        float4 f0 = *(const float4*)src;
        float4 f1 = *(const float4*)(src + 4);
        uint4 u;
        u.x = pack2(f0.x, f0.y); u.y = pack2(f0.z, f0.w);
        u.z = pack2(f1.x, f1.y); u.w = pack2(f1.z, f1.w);
        *(uint4*)(Qs + row * HST + grp * 8) = u;
    }

    // per-thread staging slots for K/V: 2 tasks of (row,grp)
    const int srow0 = tid >> 3;          // 0..31
    const int sgrp  = tid & 7;
    float4 kr[2][2], vr[2][2];

    // preload K tile 0 (loop1 only needs K)
    #pragma unroll
    for (int it = 0; it < 2; it++) {
        const float* src = Kp + (size_t)(srow0 + 32 * it) * DKDIM + sgrp * 8;
        kr[it][0] = *(const float4*)src;
        kr[it][1] = *(const float4*)(src + 4);
    }

    const float scale = 0.125f;
    float rsum[2][2] = {{0.f, 0.f}, {0.f, 0.f}};

    // lane-pattern constants for ldmatrix
    const int a_row = (lane & 15);
    const int a_col = (lane >> 4) << 3;
    const int bk_row = ((lane >> 4) << 3) + (lane & 7);   // K (no trans)
    const int bk_col = ((lane >> 3) & 1) << 3;
    const int bv_row = (((lane >> 3) & 1) << 3) + (lane & 7);  // V (trans)
    const int bv_col = (lane >> 4) << 3;

    __syncthreads();  // Qs ready

    // ================= LOOP 1: rowsums =================
    for (int kt = 0; kt < 32; kt++) {
        #pragma unroll
        for (int it = 0; it < 2; it++) {
            uint4 u;
            u.x = pack2(kr[it][0].x, kr[it][0].y); u.y = pack2(kr[it][0].z, kr[it][0].w);
            u.z = pack2(kr[it][1].x, kr[it][1].y); u.w = pack2(kr[it][1].z, kr[it][1].w);
            *(uint4*)(Ks + (srow0 + 32 * it) * HST + sgrp * 8) = u;
        }
        __syncthreads();

        if (kt + 1 < 32) {
            const float* Kn = Kp + (size_t)(kt + 1) * 64 * DKDIM;
            #pragma unroll
            for (int it = 0; it < 2; it++) {
                const float* src = Kn + (size_t)(srow0 + 32 * it) * DKDIM + sgrp * 8;
                kr[it][0] = *(const float4*)src;
                kr[it][1] = *(const float4*)(src + 4);
            }
        }

        float accS[2][4][4];
        #pragma unroll
        for (int i = 0; i < 2; i++)
            #pragma unroll
            for (int j = 0; j < 4; j++)
                #pragma unroll
                for (int t = 0; t < 4; t++) accS[i][j][t] = 0.f;

        #pragma unroll
        for (int d0 = 0; d0 < DKDIM; d0 += 16) {
            uint32_t a[2][4], bb[2][4];
            #pragma unroll
            for (int i = 0; i < 2; i++)
                ldsm4(a[i], Qs + (wq * 32 + i * 16 + a_row) * HST + d0 + a_col);
            #pragma unroll
            for (int nb = 0; nb < 2; nb++)
                ldsm4(bb[nb], Ks + (wk * 32 + nb * 16 + bk_row) * HST + d0 + bk_col);
            #pragma unroll
            for (int i = 0; i < 2; i++)
                #pragma unroll
                for (int nb = 0; nb < 2; nb++) {
                    mma_f16(accS[i][nb * 2 + 0], a[i], bb[nb][0], bb[nb][1]);
                    mma_f16(accS[i][nb * 2 + 1], a[i], bb[nb][2], bb[nb][3]);
                }
        }

        // mask + exp + rowsum (no stores)
        #pragma unroll
        for (int i = 0; i < 2; i++) {
            #pragma unroll
            for (int rr = 0; rr < 2; rr++) {
                const int rl = wq * 32 + i * 16 + rr * 8 + gid;
                const int* mrow = mask + ((size_t)b * SEQ + q0 + rl) * SEQ + kt * 64;
                #pragma unroll
                for (int j = 0; j < 4; j++) {
                    const int c = wk * 32 + j * 8 + 2 * tig;
                    int2 m = *(const int2*)(mrow + c);
                    float e0 = m.x ? __expf(accS[i][j][rr * 2 + 0] * scale) : 0.f;
                    float e1 = m.y ? __expf(accS[i][j][rr * 2 + 1] * scale) : 0.f;
                    rsum[i][rr] += e0 + e1;
                }
            }
        }
        __syncthreads();  // Ks consumed
    }

    // ---- reduce rowsums -> invs ----
    #pragma unroll
    for (int i = 0; i < 2; i++)
        #pragma unroll
        for (int rr = 0; rr < 2; rr++) {
            float r = rsum[i][rr];
            r += __shfl_xor_sync(0xffffffffu, r, 1);
            r += __shfl_xor_sync(0xffffffffu, r, 2);
            if (tig == 0)
                rs[(wq * 32 + i * 16 + rr * 8 + gid) * 2 + wk] = r;
        }
    __syncthreads();
    if (tid < 128)
        invs[tid] = 1.0f / (rs[2 * tid] + rs[2 * tid + 1]);
    __syncthreads();

    float invR[2][2];
    #pragma unroll
    for (int i = 0; i < 2; i++)
        #pragma unroll
        for (int rr = 0; rr < 2; rr++)
            invR[i][rr] = invs[wq * 32 + i * 16 + rr * 8 + gid];

    // preload K+V tile 0 for loop2
    #pragma unroll
    for (int it = 0; it < 2; it++) {
        const float* ks = Kp + (size_t)(srow0 + 32 * it) * DKDIM + sgrp * 8;
        kr[it][0] = *(const float4*)ks;
        kr[it][1] = *(const float4*)(ks + 4);
        const float* vs = Vp + (size_t)(srow0 + 32 * it) * DKDIM + sgrp * 8;
        vr[it][0] = *(const float4*)vs;
        vr[it][1] = *(const float4*)(vs + 4);
    }

    float accO[2][4][4];
    #pragma unroll
    for (int i = 0; i < 2; i++)
        #pragma unroll
        for (int j = 0; j < 4; j++)
            #pragma unroll
            for (int t = 0; t < 4; t++) accO[i][j][t] = 0.f;

    // ================= LOOP 2: W + O =================
    for (int kt = 0; kt < 32; kt++) {
        #pragma unroll
        for (int it = 0; it < 2; it++) {
            uint4 u;
            u.x = pack2(kr[it][0].x, kr[it][0].y); u.y = pack2(kr[it][0].z, kr[it][0].w);
            u.z = pack2(kr[it][1].x, kr[it][1].y); u.w = pack2(kr[it][1].z, kr[it][1].w);
            *(uint4*)(Ks + (srow0 + 32 * it) * HST + sgrp * 8) = u;
            uint4 v;
            v.x = pack2(vr[it][0].x, vr[it][0].y); v.y = pack2(vr[it][0].z, vr[it][0].w);
            v.z = pack2(vr[it][1].x, vr[it][1].y); v.w = pack2(vr[it][1].z, vr[it][1].w);
            *(uint4*)(Vs + (srow0 + 32 * it) * HST + sgrp * 8) = v;
        }
        __syncthreads();

        if (kt + 1 < 32) {
            const float* Kn = Kp + (size_t)(kt + 1) * 64 * DKDIM;
            const float* Vn = Vp + (size_t)(kt + 1) * 64 * DKDIM;
            #pragma unroll
            for (int it = 0; it < 2; it++) {
                const float* ks = Kn + (size_t)(srow0 + 32 * it) * DKDIM + sgrp * 8;
                kr[it][0] = *(const float4*)ks;
                kr[it][1] = *(const float4*)(ks + 4);
                const float* vs = Vn + (size_t)(srow0 + 32 * it) * DKDIM + sgrp * 8;
                vr[it][0] = *(const float4*)vs;
                vr[it][1] = *(const float4*)(vs + 4);
            }
        }

        float accS[2][4][4];
        #pragma unroll
        for (int i = 0; i < 2; i++)
            #pragma unroll
            for (int j = 0; j < 4; j++)
                #pragma unroll
                for (int t = 0; t < 4; t++) accS[i][j][t] = 0.f;

        #pragma unroll
        for (int d0 = 0; d0 < DKDIM; d0 += 16) {
            uint32_t a[2][4], bb[2][4];
            #pragma unroll
            for (int i = 0; i < 2; i++)
                ldsm4(a[i], Qs + (wq * 32 + i * 16 + a_row) * HST + d0 + a_col);
            #pragma unroll
            for (int nb = 0; nb < 2; nb++)
                ldsm4(bb[nb], Ks + (wk * 32 + nb * 16 + bk_row) * HST + d0 + bk_col);
            #pragma unroll
            for (int i = 0; i < 2; i++)
                #pragma unroll
                for (int nb = 0; nb < 2; nb++) {
                    mma_f16(accS[i][nb * 2 + 0], a[i], bb[nb][0], bb[nb][1]);
                    mma_f16(accS[i][nb * 2 + 1], a[i], bb[nb][2], bb[nb][3]);
                }
        }

        // epilogue: normalized w -> W (global) + Ss (fp16)
        #pragma unroll
        for (int i = 0; i < 2; i++) {
            #pragma unroll
            for (int rr = 0; rr < 2; rr++) {
                const int rl = wq * 32 + i * 16 + rr * 8 + gid;
                const float iv = invR[i][rr];
                const int* mrow = mask + ((size_t)b * SEQ + q0 + rl) * SEQ + kt * 64;
                float*    wrow = W    + ((size_t)bh * SEQ + q0 + rl) * SEQ + kt * 64;
                __half* ssrow = Ss + rl * HST;
                #pragma unroll
                for (int j = 0; j < 4; j++) {
                    const int c = wk * 32 + j * 8 + 2 * tig;
                    int2 m = *(const int2*)(mrow + c);
                    float w0 = m.x ? __expf(accS[i][j][rr * 2 + 0] * scale) * iv : 0.f;
                    float w1 = m.y ? __expf(accS[i][j][rr * 2 + 1] * scale) * iv : 0.f;
                    *(float2*)(wrow + c) = make_float2(w0, w1);
                    *(uint32_t*)(ssrow + c) = pack2(w0, w1);
                }
            }
        }
        __syncthreads();  // Ss ready

        // mma2: accO += Ss @ Vs
        #pragma unroll
        for (int k0 = 0; k0 < 64; k0 += 16) {
            uint32_t a[2][4], bb[2][4];
            #pragma unroll
            for (int i = 0; i < 2; i++)
                ldsm4(a[i], Ss + (wq * 32 + i * 16 + a_row) * HST + k0 + a_col);
            #pragma unroll
            for (int nb = 0; nb < 2; nb++)
                ldsm4t(bb[nb], Vs + (k0 + bv_row) * HST + wk * 32 + nb * 16 + bv_col);
            #pragma unroll
            for (int i = 0; i < 2; i++)
                #pragma unroll
                for (int nb = 0; nb < 2; nb++) {
                    mma_f16(accO[i][nb * 2 + 0], a[i], bb[nb][0], bb[nb][1]);
                    mma_f16(accO[i][nb * 2 + 1], a[i], bb[nb][2], bb[nb][3]);
                }
        }
        __syncthreads();  // Ks/Vs/Ss consumed
    }

    // ---- store O (already normalized) ----
    #pragma unroll
    for (int i = 0; i < 2; i++) {
        #pragma unroll
        for (int rr = 0; rr < 2; rr++) {
            const int rl = wq * 32 + i * 16 + rr * 8 + gid;
            float* orow = O + ((size_t)bh * SEQ + q0 + rl) * DKDIM + wk * 32;
            #pragma unroll
            for (int j = 0; j < 4; j++) {
                float2 v;
                v.x = accO[i][j][rr * 2 + 0];
                v.y = accO[i][j][rr * 2 + 1];
                *(float2*)(orow + j * 8 + 2 * tig) = v;
            }
        }
    }
}

// ---------------------------------------------------------------------------
extern "C" void kernel_launch(void* const* d_in, const int* in_sizes, int n_in,
                              void* d_out, int out_size)
{
    const float* Q    = (const float*)d_in[0];
    const float* K    = (const float*)d_in[1];
    const float* V    = (const float*)d_in[2];
    const int*   mask = (const int*)  d_in[3];

    float* O = (float*)d_out;                                        // [B,H,S,DK]
    float* W = (float*)d_out + (size_t)BATCH * HEADS * SEQ * DKDIM;  // [B,H,S,S]

    const int smem = (128 * HST + 64 * HST + 64 * HST + 128 * HST) * 2  // halves
                   + (256 + 128) * 4;                                   // floats
    cudaFuncSetAttribute(sdpa_fused_kernel,
                         cudaFuncAttributeMaxDynamicSharedMemorySize, smem);

    dim3 grid(SEQ / 128, BATCH * HEADS);
    sdpa_fused_kernel<<<grid, 256, smem>>>(Q, K, V, mask, W, O);
}

// round 8
// speedup vs baseline: 2.1165x; 2.1165x over previous
#include <cuda_runtime.h>
#include <cuda_fp16.h>
#include <math.h>
#include <stdint.h>

// B=2, H=16, S=2048, DK=64
// Inputs: Q[B,H,S,DK] f32, K[B,H,S,DK] f32, V[B,H,S,DK] f32, mask[B,1,S,S] i32
// Output: concat( O[B,H,S,DK] f32, W[B,H,S,S] f32 )

#define BATCH 2
#define HEADS 16
#define SEQ   2048
#define DKDIM 64
#define NELEM ((size_t)BATCH * HEADS * SEQ * DKDIM)   // 4,194,304

#define HST 72   // half-element stride (144B rows; 9x16B -> cp.async aligned, ldmatrix conflict-free)

__device__ __half g_Qh[NELEM];
__device__ __half g_Kh[NELEM];
__device__ __half g_Vh[NELEM];
__device__ float  g_inv[(size_t)BATCH * HEADS * SEQ];

// ---------------------------------------------------------------------------
__device__ __forceinline__ uint32_t pack2(float a, float b) {
    __half2 h = __floats2half2_rn(a, b);
    return *(uint32_t*)&h;
}

__device__ __forceinline__ void cp16(void* smem, const void* gmem) {
    uint32_t s = (uint32_t)__cvta_generic_to_shared(smem);
    asm volatile("cp.async.cg.shared.global [%0], [%1], 16;" :: "r"(s), "l"(gmem));
}
__device__ __forceinline__ void cp_commit() {
    asm volatile("cp.async.commit_group;");
}
__device__ __forceinline__ void cp_wait1() {
    asm volatile("cp.async.wait_group 1;");
}

__device__ __forceinline__ void ldsm4(uint32_t r[4], const __half* p) {
    uint32_t addr = (uint32_t)__cvta_generic_to_shared(p);
    asm volatile("ldmatrix.sync.aligned.m8n8.x4.shared.b16 {%0,%1,%2,%3}, [%4];"
                 : "=r"(r[0]), "=r"(r[1]), "=r"(r[2]), "=r"(r[3]) : "r"(addr));
}
__device__ __forceinline__ void ldsm4t(uint32_t r[4], const __half* p) {
    uint32_t addr = (uint32_t)__cvta_generic_to_shared(p);
    asm volatile("ldmatrix.sync.aligned.m8n8.x4.trans.shared.b16 {%0,%1,%2,%3}, [%4];"
                 : "=r"(r[0]), "=r"(r[1]), "=r"(r[2]), "=r"(r[3]) : "r"(addr));
}
__device__ __forceinline__ void mma_f16(float c[4], const uint32_t a[4],
                                        uint32_t b0, uint32_t b1) {
    asm volatile(
        "mma.sync.aligned.m16n8k16.row.col.f32.f16.f16.f32 "
        "{%0,%1,%2,%3}, {%4,%5,%6,%7}, {%8,%9}, {%0,%1,%2,%3};\n"
        : "+f"(c[0]), "+f"(c[1]), "+f"(c[2]), "+f"(c[3])
        : "r"(a[0]), "r"(a[1]), "r"(a[2]), "r"(a[3]), "r"(b0), "r"(b1));
}

// ---------------------------------------------------------------------------
// Pre-convert Q/K/V f32 -> fp16. 2048 blocks x 256 thr x 8 elems.
// ---------------------------------------------------------------------------
__global__ __launch_bounds__(256)
void convert_kernel(const float* __restrict__ Q,
                    const float* __restrict__ K,
                    const float* __restrict__ V)
{
    const size_t i = ((size_t)blockIdx.x * 256 + threadIdx.x) * 8;
    {
        float4 a = *(const float4*)(Q + i), b = *(const float4*)(Q + i + 4);
        uint4 u = { pack2(a.x, a.y), pack2(a.z, a.w), pack2(b.x, b.y), pack2(b.z, b.w) };
        *(uint4*)(g_Qh + i) = u;
    }
    {
        float4 a = *(const float4*)(K + i), b = *(const float4*)(K + i + 4);
        uint4 u = { pack2(a.x, a.y), pack2(a.z, a.w), pack2(b.x, b.y), pack2(b.z, b.w) };
        *(uint4*)(g_Kh + i) = u;
    }
    {
        float4 a = *(const float4*)(V + i), b = *(const float4*)(V + i + 4);
        uint4 u = { pack2(a.x, a.y), pack2(a.z, a.w), pack2(b.x, b.y), pack2(b.z, b.w) };
        *(uint4*)(g_Vh + i) = u;
    }
}

// ---------------------------------------------------------------------------
// Fused: per (bh, 128-q tile), loop 32 k-tiles of 64:
//   mma1 S=QK^T, e=mask?exp(S/8):0, STG e->W (unnormalized), STS fp16 e->Ss,
//   mma2 accO += e @ V.  End: inv=1/rowsum, O=accO*inv, g_inv=inv.
// 8 warps 4(q) x 2(k|n), warp tiles 32x32. K/V double-buffered via cp.async.
// ---------------------------------------------------------------------------
__global__ __launch_bounds__(256, 2)
void sdpa_fused_kernel(const int* __restrict__ mask,
                       float* __restrict__ W,
                       float* __restrict__ O)
{
    extern __shared__ __align__(16) char smraw[];
    __half* Qs = (__half*)smraw;              // [128][HST]
    __half* Ks = Qs + 128 * HST;              // [2][64][HST]
    __half* Vs = Ks + 2 * 64 * HST;           // [2][64][HST]
    __half* Ss = Vs + 2 * 64 * HST;           // [128][HST]
    float*  rs   = (float*)(Ss + 128 * HST);  // [128][2]
    float*  invs = rs + 256;                  // [128]

    const int bh   = blockIdx.y;
    const int b    = bh >> 4;
    const int q0   = blockIdx.x * 128;
    const int tid  = threadIdx.x;
    const int lane = tid & 31;
    const int warp = tid >> 5;
    const int wq   = warp >> 1;   // 0..3
    const int wk   = warp & 1;    // 0..1
    const int gid  = lane >> 2;
    const int tig  = lane & 3;

    const __half* Qp = g_Qh + ((size_t)bh * SEQ + q0) * DKDIM;
    const __half* Kp = g_Kh + (size_t)bh * SEQ * DKDIM;
    const __half* Vp = g_Vh + (size_t)bh * SEQ * DKDIM;

    const int crow = tid >> 3;   // 0..31  (chunk row base)
    const int cgrp = tid & 7;    // 16B chunk within row

    // prologue: Q tile (4 chunks/thr) + K0/V0 (2 chunks/thr each), one group
    #pragma unroll
    for (int it = 0; it < 4; it++) {
        const int id  = tid + it * 256;
        const int row = id >> 3;
        cp16(Qs + row * HST + cgrp * 8, Qp + row * DKDIM + cgrp * 8);
    }
    #pragma unroll
    for (int it = 0; it < 2; it++) {
        const int row = crow + 32 * it;
        cp16(Ks + row * HST + cgrp * 8, Kp + (size_t)row * DKDIM + cgrp * 8);
        cp16(Vs + row * HST + cgrp * 8, Vp + (size_t)row * DKDIM + cgrp * 8);
    }
    cp_commit();

    const float scale = 0.125f;
    float rsum[2][2] = {{0.f, 0.f}, {0.f, 0.f}};

    float accO[2][4][4];
    #pragma unroll
    for (int i = 0; i < 2; i++)
        #pragma unroll
        for (int j = 0; j < 4; j++)
            #pragma unroll
            for (int t = 0; t < 4; t++) accO[i][j][t] = 0.f;

    // ldmatrix lane patterns
    const int a_row  = (lane & 15);
    const int a_col  = (lane >> 4) << 3;
    const int bk_row = ((lane >> 4) << 3) + (lane & 7);
    const int bk_col = ((lane >> 3) & 1) << 3;
    const int bv_row = (((lane >> 3) & 1) << 3) + (lane & 7);
    const int bv_col = (lane >> 4) << 3;

    for (int kt = 0; kt < 32; kt++) {
        const int buf = kt & 1;
        // issue next tile into other buffer
        if (kt + 1 < 32) {
            const int nb = (kt + 1) & 1;
            const __half* Kn = Kp + (size_t)(kt + 1) * 64 * DKDIM;
            const __half* Vn = Vp + (size_t)(kt + 1) * 64 * DKDIM;
            #pragma unroll
            for (int it = 0; it < 2; it++) {
                const int row = crow + 32 * it;
                cp16(Ks + (nb * 64 + row) * HST + cgrp * 8, Kn + (size_t)row * DKDIM + cgrp * 8);
                cp16(Vs + (nb * 64 + row) * HST + cgrp * 8, Vn + (size_t)row * DKDIM + cgrp * 8);
            }
        }
        cp_commit();
        cp_wait1();          // current tile (and Q on kt=0) complete
        __syncthreads();

        const __half* Kb = Ks + buf * 64 * HST;
        const __half* Vb = Vs + buf * 64 * HST;

        // ---- mma1: S = Q @ K^T ----
        float accS[2][4][4];
        #pragma unroll
        for (int i = 0; i < 2; i++)
            #pragma unroll
            for (int j = 0; j < 4; j++)
                #pragma unroll
                for (int t = 0; t < 4; t++) accS[i][j][t] = 0.f;

        #pragma unroll
        for (int d0 = 0; d0 < DKDIM; d0 += 16) {
            uint32_t a[2][4], bb[2][4];
            #pragma unroll
            for (int i = 0; i < 2; i++)
                ldsm4(a[i], Qs + (wq * 32 + i * 16 + a_row) * HST + d0 + a_col);
            #pragma unroll
            for (int nb = 0; nb < 2; nb++)
                ldsm4(bb[nb], Kb + (wk * 32 + nb * 16 + bk_row) * HST + d0 + bk_col);
            #pragma unroll
            for (int i = 0; i < 2; i++)
                #pragma unroll
                for (int nb = 0; nb < 2; nb++) {
                    mma_f16(accS[i][nb * 2 + 0], a[i], bb[nb][0], bb[nb][1]);
                    mma_f16(accS[i][nb * 2 + 1], a[i], bb[nb][2], bb[nb][3]);
                }
        }

        // ---- epilogue: exp + mask, STG W (unnormalized), STS Ss, rowsum ----
        #pragma unroll
        for (int i = 0; i < 2; i++) {
            #pragma unroll
            for (int rr = 0; rr < 2; rr++) {
                const int rl = wq * 32 + i * 16 + rr * 8 + gid;
                const int* mrow = mask + ((size_t)b * SEQ + q0 + rl) * SEQ + kt * 64;
                float*    wrow = W    + ((size_t)bh * SEQ + q0 + rl) * SEQ + kt * 64;
                __half* ssrow = Ss + rl * HST;
                #pragma unroll
                for (int j = 0; j < 4; j++) {
                    const int c = wk * 32 + j * 8 + 2 * tig;
                    int2 m = *(const int2*)(mrow + c);
                    float e0 = m.x ? __expf(accS[i][j][rr * 2 + 0] * scale) : 0.f;
                    float e1 = m.y ? __expf(accS[i][j][rr * 2 + 1] * scale) : 0.f;
                    *(float2*)(wrow + c) = make_float2(e0, e1);
                    *(uint32_t*)(ssrow + c) = pack2(e0, e1);
                    rsum[i][rr] += e0 + e1;
                }
            }
        }
        __syncthreads();   // Ss ready

        // ---- mma2: accO += Ss @ Vs ----
        #pragma unroll
        for (int k0 = 0; k0 < 64; k0 += 16) {
            uint32_t a[2][4], bb[2][4];
            #pragma unroll
            for (int i = 0; i < 2; i++)
                ldsm4(a[i], Ss + (wq * 32 + i * 16 + a_row) * HST + k0 + a_col);
            #pragma unroll
            for (int nb = 0; nb < 2; nb++)
                ldsm4t(bb[nb], Vb + (k0 + bv_row) * HST + wk * 32 + nb * 16 + bv_col);
            #pragma unroll
            for (int i = 0; i < 2; i++)
                #pragma unroll
                for (int nb = 0; nb < 2; nb++) {
                    mma_f16(accO[i][nb * 2 + 0], a[i], bb[nb][0], bb[nb][1]);
                    mma_f16(accO[i][nb * 2 + 1], a[i], bb[nb][2], bb[nb][3]);
                }
        }
        __syncthreads();   // Ss / K,V buffer consumed
    }

    // ---- rowsums -> inv ----
    #pragma unroll
    for (int i = 0; i < 2; i++)
        #pragma unroll
        for (int rr = 0; rr < 2; rr++) {
            float r = rsum[i][rr];
            r += __shfl_xor_sync(0xffffffffu, r, 1);
            r += __shfl_xor_sync(0xffffffffu, r, 2);
            if (tig == 0)
                rs[(wq * 32 + i * 16 + rr * 8 + gid) * 2 + wk] = r;
        }
    __syncthreads();
    if (tid < 128) {
        const float iv = 1.0f / (rs[2 * tid] + rs[2 * tid + 1]);
        invs[tid] = iv;
        g_inv[(size_t)bh * SEQ + q0 + tid] = iv;
    }
    __syncthreads();

    // ---- store O = accO * inv ----
    #pragma unroll
    for (int i = 0; i < 2; i++) {
        #pragma unroll
        for (int rr = 0; rr < 2; rr++) {
            const int rl = wq * 32 + i * 16 + rr * 8 + gid;
            const float iv = invs[rl];
            float* orow = O + ((size_t)bh * SEQ + q0 + rl) * DKDIM + wk * 32;
            #pragma unroll
            for (int j = 0; j < 4; j++) {
                float2 v;
                v.x = accO[i][j][rr * 2 + 0] * iv;
                v.y = accO[i][j][rr * 2 + 1] * iv;
                *(float2*)(orow + j * 8 + 2 * tig) = v;
            }
        }
    }
}

// ---------------------------------------------------------------------------
// Normalize W in place: one block per row, pure streaming (86% DRAM in R5).
// ---------------------------------------------------------------------------
__global__ __launch_bounds__(256)
void sdpa_normw_kernel(float* __restrict__ Wm)
{
    const size_t row = blockIdx.x;
    const float inv = g_inv[row];
    float4* p = (float4*)(Wm + row * SEQ);
    const int t = threadIdx.x;
    float4 a = p[t];
    float4 c = p[t + 256];
    a.x *= inv; a.y *= inv; a.z *= inv; a.w *= inv;
    c.x *= inv; c.y *= inv; c.z *= inv; c.w *= inv;
    p[t]       = a;
    p[t + 256] = c;
}

// ---------------------------------------------------------------------------
extern "C" void kernel_launch(void* const* d_in, const int* in_sizes, int n_in,
                              void* d_out, int out_size)
{
    const float* Q    = (const float*)d_in[0];
    const float* K    = (const float*)d_in[1];
    const float* V    = (const float*)d_in[2];
    const int*   mask = (const int*)  d_in[3];

    float* O = (float*)d_out;                                        // [B,H,S,DK]
    float* W = (float*)d_out + (size_t)BATCH * HEADS * SEQ * DKDIM;  // [B,H,S,S]

    const int smem = (128 * HST + 2 * 64 * HST + 2 * 64 * HST + 128 * HST) * 2
                   + (256 + 128) * 4;   // 75,264 B
    cudaFuncSetAttribute(sdpa_fused_kernel,
                         cudaFuncAttributeMaxDynamicSharedMemorySize, smem);

    {
        convert_kernel<<<NELEM / (256 * 8), 256>>>(Q, K, V);
    }
    {
        dim3 grid(SEQ / 128, BATCH * HEADS);
        sdpa_fused_kernel<<<grid, 256, smem>>>(mask, W, O);
    }
    {
        dim3 grid(BATCH * HEADS * SEQ);
        sdpa_normw_kernel<<<grid, 256>>>(W);
    }
}